// round 4
// baseline (speedup 1.0000x reference)
#include <cuda_runtime.h>
#include <cuda_bf16.h>
#include <cstdint>

// Problem constants: N=50000, E=800000, IN_DIM=128, H=8, D=16
#define NMAX   50000
#define EMAX   800000
#define SCAN_B 1024
#define BM     64        // GEMM row tile per block
#define LDA    136       // smem A stride (uint16) -> conflict-free fragments

// ---- scratch (__device__ globals; no allocation allowed) ----
__device__ float    g_z[(size_t)NMAX * 128];  // projected features z[n][c]
__device__ uint16_t g_Wbh[128 * 128];         // W^T [n][k] bf16 high part
__device__ uint16_t g_Wbl[128 * 128];         // W^T [n][k] bf16 low  part
__device__ int      g_cnt[NMAX];
__device__ int      g_off[NMAX + 1];
__device__ int      g_srcs[EMAX];
__device__ int      g_bsum[64];

// ---------------------------------------------------------------------------
__global__ void k_zero(int N) {
    int i = blockIdx.x * blockDim.x + threadIdx.x;
    if (i < N) g_cnt[i] = 0;
}

// Build Wb[n][k] = Wfc[(n>>4)][k][(n&15)] split into bf16 hi/lo.
__global__ void k_wt(const float* __restrict__ Wfc) {
    int i = blockIdx.x * blockDim.x + threadIdx.x;
    if (i < 128 * 128) {
        int n = i >> 7, k = i & 127;
        float v = Wfc[(n >> 4) * 2048 + k * 16 + (n & 15)];
        __nv_bfloat16 hi = __float2bfloat16(v);
        __nv_bfloat16 lo = __float2bfloat16(v - __bfloat162float(hi));
        g_Wbh[i] = *(uint16_t*)&hi;
        g_Wbl[i] = *(uint16_t*)&lo;
    }
}

// ---------------------------------------------------------------------------
__device__ __forceinline__ void mma_bf16(float* c, const uint32_t* a,
                                         uint32_t b0, uint32_t b1) {
    asm volatile(
        "mma.sync.aligned.m16n8k16.row.col.f32.bf16.bf16.f32 "
        "{%0,%1,%2,%3}, {%4,%5,%6,%7}, {%8,%9}, {%0,%1,%2,%3};"
        : "+f"(c[0]), "+f"(c[1]), "+f"(c[2]), "+f"(c[3])
        : "r"(a[0]), "r"(a[1]), "r"(a[2]), "r"(a[3]), "r"(b0), "r"(b1));
}

// Tensor-core GEMM: z = h @ W via 2-term bf16 split (hi*hi + hi*lo + lo*hi).
// Block = 128 thr = 4 warps, 64 rows; warp owns a 16-row stripe, all 128 cols.
__global__ __launch_bounds__(128) void k_gemm_mma(const float* __restrict__ h, int N) {
    __shared__ uint16_t sAh[BM * LDA];
    __shared__ uint16_t sAl[BM * LDA];
    int base = blockIdx.x * BM;

    // Cooperative load h tile (fp32) -> split -> smem (bf16 hi/lo).
    const float4* h4 = (const float4*)h;
    for (int i = threadIdx.x; i < BM * 32; i += 128) {
        int r = i >> 5, c4 = i & 31;
        float4 v = make_float4(0.f, 0.f, 0.f, 0.f);
        if (base + r < N) v = h4[(size_t)(base + r) * 32 + c4];
        float vv[4] = {v.x, v.y, v.z, v.w};
        uint32_t ph[2], pl[2];
        uint16_t hx[4], lx[4];
#pragma unroll
        for (int j = 0; j < 4; j++) {
            __nv_bfloat16 hi = __float2bfloat16(vv[j]);
            __nv_bfloat16 lo = __float2bfloat16(vv[j] - __bfloat162float(hi));
            hx[j] = *(uint16_t*)&hi; lx[j] = *(uint16_t*)&lo;
        }
        ph[0] = (uint32_t)hx[0] | ((uint32_t)hx[1] << 16);
        ph[1] = (uint32_t)hx[2] | ((uint32_t)hx[3] << 16);
        pl[0] = (uint32_t)lx[0] | ((uint32_t)lx[1] << 16);
        pl[1] = (uint32_t)lx[2] | ((uint32_t)lx[3] << 16);
        int off = r * LDA + c4 * 4;
        *(uint2*)&sAh[off] = make_uint2(ph[0], ph[1]);
        *(uint2*)&sAl[off] = make_uint2(pl[0], pl[1]);
    }
    __syncthreads();

    int warp = threadIdx.x >> 5, lane = threadIdx.x & 31;
    int g = lane >> 2, t = lane & 3;
    int row = warp * 16 + g;

    float acc[16][4];
#pragma unroll
    for (int i = 0; i < 16; i++)
#pragma unroll
        for (int j = 0; j < 4; j++) acc[i][j] = 0.f;

    const uint32_t* Wh = (const uint32_t*)g_Wbh;   // [128][64] uint32 (2 bf16/k-pair)
    const uint32_t* Wl = (const uint32_t*)g_Wbl;

#pragma unroll
    for (int k0 = 0; k0 < 8; k0++) {
        int c = k0 * 16 + t * 2;
        uint32_t ah[4], al[4];
        ah[0] = *(const uint32_t*)&sAh[row * LDA + c];
        ah[1] = *(const uint32_t*)&sAh[(row + 8) * LDA + c];
        ah[2] = *(const uint32_t*)&sAh[row * LDA + c + 8];
        ah[3] = *(const uint32_t*)&sAh[(row + 8) * LDA + c + 8];
        al[0] = *(const uint32_t*)&sAl[row * LDA + c];
        al[1] = *(const uint32_t*)&sAl[(row + 8) * LDA + c];
        al[2] = *(const uint32_t*)&sAl[row * LDA + c + 8];
        al[3] = *(const uint32_t*)&sAl[(row + 8) * LDA + c + 8];
#pragma unroll
        for (int n0 = 0; n0 < 16; n0++) {
            int bi = (n0 * 8 + g) * 64 + k0 * 8 + t;
            uint32_t bh0 = Wh[bi], bh1 = Wh[bi + 4];
            uint32_t bl0 = Wl[bi], bl1 = Wl[bi + 4];
            mma_bf16(acc[n0], ah, bh0, bh1);
            mma_bf16(acc[n0], ah, bl0, bl1);
            mma_bf16(acc[n0], al, bh0, bh1);
        }
    }

    // Store: c0,c1 -> C[g][2t..2t+1]; c2,c3 -> C[g+8][...]
    float2* z2 = (float2*)g_z;
    int r0 = base + row, r1 = r0 + 8;
    if (r0 < N) {
#pragma unroll
        for (int n0 = 0; n0 < 16; n0++)
            z2[(size_t)r0 * 64 + n0 * 4 + t] = make_float2(acc[n0][0], acc[n0][1]);
    }
    if (r1 < N) {
#pragma unroll
        for (int n0 = 0; n0 < 16; n0++)
            z2[(size_t)r1 * 64 + n0 * 4 + t] = make_float2(acc[n0][2], acc[n0][3]);
    }
}

// ---------------------------------------------------------------------------
// Histogram: 4 edges per thread via int4.
__global__ void k_hist(const int* __restrict__ dst, int E) {
    int i = blockIdx.x * blockDim.x + threadIdx.x;
    int e4 = E >> 2;
    if (i < e4) {
        int4 d = ((const int4*)dst)[i];
        atomicAdd(&g_cnt[d.x], 1);
        atomicAdd(&g_cnt[d.y], 1);
        atomicAdd(&g_cnt[d.z], 1);
        atomicAdd(&g_cnt[d.w], 1);
    }
    int rem = e4 * 4 + i;
    if (i < (E & 3) && rem < E) atomicAdd(&g_cnt[dst[rem]], 1);
}

__global__ __launch_bounds__(SCAN_B) void k_scanA(int N) {
    __shared__ int wsum[32];
    int i = blockIdx.x * SCAN_B + threadIdx.x;
    int lane = threadIdx.x & 31, wid = threadIdx.x >> 5;
    int x = (i < N) ? g_cnt[i] : 0;
#pragma unroll
    for (int d = 1; d < 32; d <<= 1) {
        int y = __shfl_up_sync(0xFFFFFFFFu, x, d);
        if (lane >= d) x += y;
    }
    if (lane == 31) wsum[wid] = x;
    __syncthreads();
    if (wid == 0) {
        int s = wsum[lane];
#pragma unroll
        for (int d = 1; d < 32; d <<= 1) {
            int y = __shfl_up_sync(0xFFFFFFFFu, s, d);
            if (lane >= d) s += y;
        }
        wsum[lane] = s;
    }
    __syncthreads();
    int incl = x + (wid ? wsum[wid - 1] : 0);
    if (i < N) g_off[i] = incl;
    if (threadIdx.x == SCAN_B - 1) g_bsum[blockIdx.x] = incl;
}

__global__ __launch_bounds__(SCAN_B) void k_scanC(int N, int E) {
    __shared__ int sprefix;
    {
        int t = threadIdx.x;
        if (t == 0) sprefix = 0;
        __syncthreads();
        int v = (t < 64 && t < (int)blockIdx.x) ? g_bsum[t] : 0;
        if (t < 64) {
#pragma unroll
            for (int d = 16; d > 0; d >>= 1) v += __shfl_down_sync(0xFFFFFFFFu, v, d);
            if ((t & 31) == 0 && v) atomicAdd(&sprefix, v);
        }
    }
    __syncthreads();
    int prefix = sprefix;

    int i = blockIdx.x * SCAN_B + threadIdx.x;
    if (i < N) {
        int excl = g_off[i] - g_cnt[i] + prefix;
        g_off[i] = excl;
        g_cnt[i] = excl;
    }
    if (i == 0) g_off[N] = E;
}

// Scatter: 4 edges per thread via int4.
__global__ void k_scatter(const int* __restrict__ src, const int* __restrict__ dst, int E) {
    int i = blockIdx.x * blockDim.x + threadIdx.x;
    int e4 = E >> 2;
    if (i < e4) {
        int4 d = ((const int4*)dst)[i];
        int4 s = ((const int4*)src)[i];
        g_srcs[atomicAdd(&g_cnt[d.x], 1)] = s.x;
        g_srcs[atomicAdd(&g_cnt[d.y], 1)] = s.y;
        g_srcs[atomicAdd(&g_cnt[d.z], 1)] = s.z;
        g_srcs[atomicAdd(&g_cnt[d.w], 1)] = s.w;
    }
    int rem = e4 * 4 + i;
    if (i < (E & 3) && rem < E)
        g_srcs[atomicAdd(&g_cnt[dst[rem]], 1)] = src[rem];
}

// ---------------------------------------------------------------------------
// One warp per dst node; lane owns 4 channels. Softmax without max-shift.
__global__ __launch_bounds__(256) void k_agg(const float* __restrict__ h,
                                             const float* __restrict__ snorm,
                                             float* __restrict__ out, int N) {
    int gw = (blockIdx.x * 256 + threadIdx.x) >> 5;
    int lane = threadIdx.x & 31;
    if (gw >= N) return;

    const float4* z4 = (const float4*)g_z;
    float4 zd = z4[(size_t)gw * 32 + lane];
    int beg = g_off[gw], end = g_off[gw + 1];

    float4 se = make_float4(0.f,0.f,0.f,0.f);
    float4 sz = se;

#define ACC(zs) { float t; \
    t = __expf((zs).x * zd.x); se.x += t; sz.x += t * (zs).x; \
    t = __expf((zs).y * zd.y); se.y += t; sz.y += t * (zs).y; \
    t = __expf((zs).z * zd.z); se.z += t; sz.z += t * (zs).z; \
    t = __expf((zs).w * zd.w); se.w += t; sz.w += t * (zs).w; }

    int e = beg;
    for (; e + 3 < end; e += 4) {
        int s0 = g_srcs[e + 0], s1 = g_srcs[e + 1];
        int s2 = g_srcs[e + 2], s3 = g_srcs[e + 3];
        float4 q0 = z4[(size_t)s0 * 32 + lane];
        float4 q1 = z4[(size_t)s1 * 32 + lane];
        float4 q2 = z4[(size_t)s2 * 32 + lane];
        float4 q3 = z4[(size_t)s3 * 32 + lane];
        ACC(q0) ACC(q1) ACC(q2) ACC(q3)
    }
    for (; e < end; e++) {
        float4 q = z4[(size_t)g_srcs[e] * 32 + lane];
        ACC(q)
    }
#undef ACC

    float sn = snorm[gw];
    float4 hv = ((const float4*)h)[(size_t)gw * 32 + lane];
    bool has = (end > beg);
    float4 o;
#define ELU_CH(c) { float a = has ? (sz.c / se.c) : 0.f; a *= sn; \
                    o.c = hv.c + (a > 0.f ? a : expm1f(a)); }
    ELU_CH(x) ELU_CH(y) ELU_CH(z) ELU_CH(w)
#undef ELU_CH
    ((float4*)out)[(size_t)gw * 32 + lane] = o;
}

// ---------------------------------------------------------------------------
extern "C" void kernel_launch(void* const* d_in, const int* in_sizes, int n_in,
                              void* d_out, int out_size) {
    const float* h     = (const float*)d_in[0];
    const float* snorm = (const float*)d_in[1];
    const float* Wfc   = (const float*)d_in[2];
    const int*   src   = (const int*)d_in[3];
    const int*   dst   = (const int*)d_in[4];
    float*       out   = (float*)d_out;

    int N = in_sizes[1];
    int E = in_sizes[3];

    static cudaStream_t s2 = nullptr;
    static cudaEvent_t evFork = nullptr, evJoin = nullptr;
    if (!s2) {
        cudaStreamCreateWithFlags(&s2, cudaStreamNonBlocking);
        cudaEventCreateWithFlags(&evFork, cudaEventDisableTiming);
        cudaEventCreateWithFlags(&evJoin, cudaEventDisableTiming);
    }

    int nb = (N + SCAN_B - 1) / SCAN_B;
    int e4 = (E + 3) / 4;

    cudaEventRecord(evFork, 0);
    cudaStreamWaitEvent(s2, evFork, 0);

    // --- branch B (s2): CSR build ---
    k_zero   <<<(N + 255) / 256, 256, 0, s2>>>(N);
    k_hist   <<<(e4 + 255) / 256, 256, 0, s2>>>(dst, E);
    k_scanA  <<<nb, SCAN_B, 0, s2>>>(N);
    k_scanC  <<<nb, SCAN_B, 0, s2>>>(N, E);
    k_scatter<<<(e4 + 255) / 256, 256, 0, s2>>>(src, dst, E);
    cudaEventRecord(evJoin, s2);

    // --- branch A (default stream): tensor-core projection ---
    k_wt      <<<64, 256>>>(Wfc);
    k_gemm_mma<<<(N + BM - 1) / BM, 128>>>(h, N);

    cudaStreamWaitEvent(0, evJoin, 0);
    k_agg<<<(N + 7) / 8, 256>>>(h, snorm, out, N);
}

// round 5
// speedup vs baseline: 1.2798x; 1.2798x over previous
#include <cuda_runtime.h>
#include <cuda_bf16.h>
#include <cstdint>

// Problem constants: N=50000, E=800000, IN_DIM=128, H=8, D=16
#define NMAX   50000
#define EMAX   800000
#define SCAN_B 1024
#define BM     128       // GEMM row tile per block
#define LDA    136       // smem A stride in uint16 (=68 words) -> conflict-free
#define LDW    68        // smem W stride in uint32 words       -> conflict-free

// ---- scratch (__device__ globals; no allocation allowed) ----
__device__ float    g_z[(size_t)NMAX * 128];  // projected features z[n][c]
__device__ uint16_t g_Wbh[128 * 128];         // W^T [n][k] bf16 high part
__device__ uint16_t g_Wbl[128 * 128];         // W^T [n][k] bf16 low  part
__device__ int      g_cnt[NMAX];
__device__ int      g_off[NMAX + 1];
__device__ int      g_srcs[EMAX];
__device__ int      g_bsum[64];

// ---------------------------------------------------------------------------
__global__ void k_zero(int N) {
    int i = blockIdx.x * blockDim.x + threadIdx.x;
    if (i < N) g_cnt[i] = 0;
}

// Build Wb[n][k] = Wfc[(n>>4)][k][(n&15)] split into bf16 hi/lo.
__global__ void k_wt(const float* __restrict__ Wfc) {
    int i = blockIdx.x * blockDim.x + threadIdx.x;
    if (i < 128 * 128) {
        int n = i >> 7, k = i & 127;
        float v = Wfc[(n >> 4) * 2048 + k * 16 + (n & 15)];
        __nv_bfloat16 hi = __float2bfloat16(v);
        __nv_bfloat16 lo = __float2bfloat16(v - __bfloat162float(hi));
        g_Wbh[i] = *(uint16_t*)&hi;
        g_Wbl[i] = *(uint16_t*)&lo;
    }
}

// ---------------------------------------------------------------------------
__device__ __forceinline__ void mma_bf16(float* c, const uint32_t* a,
                                         uint32_t b0, uint32_t b1) {
    asm volatile(
        "mma.sync.aligned.m16n8k16.row.col.f32.bf16.bf16.f32 "
        "{%0,%1,%2,%3}, {%4,%5,%6,%7}, {%8,%9}, {%0,%1,%2,%3};"
        : "+f"(c[0]), "+f"(c[1]), "+f"(c[2]), "+f"(c[3])
        : "r"(a[0]), "r"(a[1]), "r"(a[2]), "r"(a[3]), "r"(b0), "r"(b1));
}

// Tensor-core GEMM: z = h @ W, 2-term bf16 split (hi*hi + hi*lo + lo*hi).
// Block = 256 thr = 8 warps, 128 rows; warp owns a 16-row stripe, all 128 cols.
// BOTH operands staged in smem (W was the R4 mistake: per-warp global loads).
__global__ __launch_bounds__(256) void k_gemm_mma(const float* __restrict__ h, int N) {
    extern __shared__ uint32_t smem[];
    uint32_t* sWh = smem;                         // [128][LDW] words
    uint32_t* sWl = sWh + 128 * LDW;
    uint16_t* sAh = (uint16_t*)(sWl + 128 * LDW); // [BM][LDA] uint16
    uint16_t* sAl = sAh + BM * LDA;

    int base = blockIdx.x * BM;

    // Stage W hi/lo: coalesced global reads, padded smem rows.
    {
        const uint32_t* Wh = (const uint32_t*)g_Wbh;  // [128][64] words
        const uint32_t* Wl = (const uint32_t*)g_Wbl;
        for (int i = threadIdx.x; i < 128 * 64; i += 256) {
            int n = i >> 6, w = i & 63;
            sWh[n * LDW + w] = Wh[i];
            sWl[n * LDW + w] = Wl[i];
        }
    }

    // Stage A tile: fp32 -> bf16 hi/lo split.
    const float4* h4 = (const float4*)h;
    for (int i = threadIdx.x; i < BM * 32; i += 256) {
        int r = i >> 5, c4 = i & 31;
        float4 v = make_float4(0.f, 0.f, 0.f, 0.f);
        if (base + r < N) v = h4[(size_t)(base + r) * 32 + c4];
        float vv[4] = {v.x, v.y, v.z, v.w};
        uint16_t hx[4], lx[4];
#pragma unroll
        for (int j = 0; j < 4; j++) {
            __nv_bfloat16 hi = __float2bfloat16(vv[j]);
            __nv_bfloat16 lo = __float2bfloat16(vv[j] - __bfloat162float(hi));
            hx[j] = *(uint16_t*)&hi; lx[j] = *(uint16_t*)&lo;
        }
        int off = r * LDA + c4 * 4;
        *(uint2*)&sAh[off] = make_uint2((uint32_t)hx[0] | ((uint32_t)hx[1] << 16),
                                        (uint32_t)hx[2] | ((uint32_t)hx[3] << 16));
        *(uint2*)&sAl[off] = make_uint2((uint32_t)lx[0] | ((uint32_t)lx[1] << 16),
                                        (uint32_t)lx[2] | ((uint32_t)lx[3] << 16));
    }
    __syncthreads();

    int warp = threadIdx.x >> 5, lane = threadIdx.x & 31;
    int g = lane >> 2, t = lane & 3;
    int row = warp * 16 + g;

    float acc[16][4];
#pragma unroll
    for (int i = 0; i < 16; i++)
#pragma unroll
        for (int j = 0; j < 4; j++) acc[i][j] = 0.f;

#pragma unroll
    for (int k0 = 0; k0 < 8; k0++) {
        int c = k0 * 16 + t * 2;
        uint32_t ah[4], al[4];
        ah[0] = *(const uint32_t*)&sAh[row * LDA + c];
        ah[1] = *(const uint32_t*)&sAh[(row + 8) * LDA + c];
        ah[2] = *(const uint32_t*)&sAh[row * LDA + c + 8];
        ah[3] = *(const uint32_t*)&sAh[(row + 8) * LDA + c + 8];
        al[0] = *(const uint32_t*)&sAl[row * LDA + c];
        al[1] = *(const uint32_t*)&sAl[(row + 8) * LDA + c];
        al[2] = *(const uint32_t*)&sAl[row * LDA + c + 8];
        al[3] = *(const uint32_t*)&sAl[(row + 8) * LDA + c + 8];
#pragma unroll
        for (int n0 = 0; n0 < 16; n0++) {
            int bi = (n0 * 8 + g) * LDW + k0 * 8 + t;
            uint32_t bh0 = sWh[bi], bh1 = sWh[bi + 4];
            uint32_t bl0 = sWl[bi], bl1 = sWl[bi + 4];
            mma_bf16(acc[n0], ah, bh0, bh1);
            mma_bf16(acc[n0], ah, bl0, bl1);
            mma_bf16(acc[n0], al, bh0, bh1);
        }
    }

    // Store: c0,c1 -> C[g][2t..2t+1]; c2,c3 -> C[g+8][...]
    float2* z2 = (float2*)g_z;
    int r0 = base + row, r1 = r0 + 8;
    if (r0 < N) {
#pragma unroll
        for (int n0 = 0; n0 < 16; n0++)
            z2[(size_t)r0 * 64 + n0 * 4 + t] = make_float2(acc[n0][0], acc[n0][1]);
    }
    if (r1 < N) {
#pragma unroll
        for (int n0 = 0; n0 < 16; n0++)
            z2[(size_t)r1 * 64 + n0 * 4 + t] = make_float2(acc[n0][2], acc[n0][3]);
    }
}

// ---------------------------------------------------------------------------
// Histogram: 4 edges per thread via int4.
__global__ void k_hist(const int* __restrict__ dst, int E) {
    int i = blockIdx.x * blockDim.x + threadIdx.x;
    int e4 = E >> 2;
    if (i < e4) {
        int4 d = ((const int4*)dst)[i];
        atomicAdd(&g_cnt[d.x], 1);
        atomicAdd(&g_cnt[d.y], 1);
        atomicAdd(&g_cnt[d.z], 1);
        atomicAdd(&g_cnt[d.w], 1);
    }
    int rem = e4 * 4 + i;
    if (i < (E & 3) && rem < E) atomicAdd(&g_cnt[dst[rem]], 1);
}

__global__ __launch_bounds__(SCAN_B) void k_scanA(int N) {
    __shared__ int wsum[32];
    int i = blockIdx.x * SCAN_B + threadIdx.x;
    int lane = threadIdx.x & 31, wid = threadIdx.x >> 5;
    int x = (i < N) ? g_cnt[i] : 0;
#pragma unroll
    for (int d = 1; d < 32; d <<= 1) {
        int y = __shfl_up_sync(0xFFFFFFFFu, x, d);
        if (lane >= d) x += y;
    }
    if (lane == 31) wsum[wid] = x;
    __syncthreads();
    if (wid == 0) {
        int s = wsum[lane];
#pragma unroll
        for (int d = 1; d < 32; d <<= 1) {
            int y = __shfl_up_sync(0xFFFFFFFFu, s, d);
            if (lane >= d) s += y;
        }
        wsum[lane] = s;
    }
    __syncthreads();
    int incl = x + (wid ? wsum[wid - 1] : 0);
    if (i < N) g_off[i] = incl;
    if (threadIdx.x == SCAN_B - 1) g_bsum[blockIdx.x] = incl;
}

__global__ __launch_bounds__(SCAN_B) void k_scanC(int N, int E) {
    __shared__ int sprefix;
    {
        int t = threadIdx.x;
        if (t == 0) sprefix = 0;
        __syncthreads();
        int v = (t < 64 && t < (int)blockIdx.x) ? g_bsum[t] : 0;
        if (t < 64) {
#pragma unroll
            for (int d = 16; d > 0; d >>= 1) v += __shfl_down_sync(0xFFFFFFFFu, v, d);
            if ((t & 31) == 0 && v) atomicAdd(&sprefix, v);
        }
    }
    __syncthreads();
    int prefix = sprefix;

    int i = blockIdx.x * SCAN_B + threadIdx.x;
    if (i < N) {
        int excl = g_off[i] - g_cnt[i] + prefix;
        g_off[i] = excl;
        g_cnt[i] = excl;
    }
    if (i == 0) g_off[N] = E;
}

// Scatter: 4 edges per thread via int4.
__global__ void k_scatter(const int* __restrict__ src, const int* __restrict__ dst, int E) {
    int i = blockIdx.x * blockDim.x + threadIdx.x;
    int e4 = E >> 2;
    if (i < e4) {
        int4 d = ((const int4*)dst)[i];
        int4 s = ((const int4*)src)[i];
        g_srcs[atomicAdd(&g_cnt[d.x], 1)] = s.x;
        g_srcs[atomicAdd(&g_cnt[d.y], 1)] = s.y;
        g_srcs[atomicAdd(&g_cnt[d.z], 1)] = s.z;
        g_srcs[atomicAdd(&g_cnt[d.w], 1)] = s.w;
    }
    int rem = e4 * 4 + i;
    if (i < (E & 3) && rem < E)
        g_srcs[atomicAdd(&g_cnt[dst[rem]], 1)] = src[rem];
}

// ---------------------------------------------------------------------------
// One warp per dst node; lane owns 4 channels. Softmax without max-shift.
__global__ __launch_bounds__(256) void k_agg(const float* __restrict__ h,
                                             const float* __restrict__ snorm,
                                             float* __restrict__ out, int N) {
    int gw = (blockIdx.x * 256 + threadIdx.x) >> 5;
    int lane = threadIdx.x & 31;
    if (gw >= N) return;

    const float4* z4 = (const float4*)g_z;
    float4 zd = z4[(size_t)gw * 32 + lane];
    int beg = g_off[gw], end = g_off[gw + 1];

    float4 se = make_float4(0.f,0.f,0.f,0.f);
    float4 sz = se;

#define ACC(zs) { float t; \
    t = __expf((zs).x * zd.x); se.x += t; sz.x += t * (zs).x; \
    t = __expf((zs).y * zd.y); se.y += t; sz.y += t * (zs).y; \
    t = __expf((zs).z * zd.z); se.z += t; sz.z += t * (zs).z; \
    t = __expf((zs).w * zd.w); se.w += t; sz.w += t * (zs).w; }

    int e = beg;
    for (; e + 3 < end; e += 4) {
        int s0 = g_srcs[e + 0], s1 = g_srcs[e + 1];
        int s2 = g_srcs[e + 2], s3 = g_srcs[e + 3];
        float4 q0 = z4[(size_t)s0 * 32 + lane];
        float4 q1 = z4[(size_t)s1 * 32 + lane];
        float4 q2 = z4[(size_t)s2 * 32 + lane];
        float4 q3 = z4[(size_t)s3 * 32 + lane];
        ACC(q0) ACC(q1) ACC(q2) ACC(q3)
    }
    for (; e < end; e++) {
        float4 q = z4[(size_t)g_srcs[e] * 32 + lane];
        ACC(q)
    }
#undef ACC

    float sn = snorm[gw];
    float4 hv = ((const float4*)h)[(size_t)gw * 32 + lane];
    bool has = (end > beg);
    float4 o;
#define ELU_CH(c) { float a = has ? (sz.c / se.c) : 0.f; a *= sn; \
                    o.c = hv.c + (a > 0.f ? a : expm1f(a)); }
    ELU_CH(x) ELU_CH(y) ELU_CH(z) ELU_CH(w)
#undef ELU_CH
    ((float4*)out)[(size_t)gw * 32 + lane] = o;
}

// ---------------------------------------------------------------------------
extern "C" void kernel_launch(void* const* d_in, const int* in_sizes, int n_in,
                              void* d_out, int out_size) {
    const float* h     = (const float*)d_in[0];
    const float* snorm = (const float*)d_in[1];
    const float* Wfc   = (const float*)d_in[2];
    const int*   src   = (const int*)d_in[3];
    const int*   dst   = (const int*)d_in[4];
    float*       out   = (float*)d_out;

    int N = in_sizes[1];
    int E = in_sizes[3];

    // smem: W hi/lo (2*128*LDW words) + A hi/lo (2*BM*LDA uint16)
    const int SMEM_GEMM = (2 * 128 * LDW) * 4 + (2 * BM * LDA) * 2;

    static cudaStream_t s2 = nullptr;
    static cudaEvent_t evFork = nullptr, evJoin = nullptr;
    if (!s2) {
        cudaStreamCreateWithFlags(&s2, cudaStreamNonBlocking);
        cudaEventCreateWithFlags(&evFork, cudaEventDisableTiming);
        cudaEventCreateWithFlags(&evJoin, cudaEventDisableTiming);
        cudaFuncSetAttribute(k_gemm_mma,
                             cudaFuncAttributeMaxDynamicSharedMemorySize, SMEM_GEMM);
    }

    int nb = (N + SCAN_B - 1) / SCAN_B;
    int e4 = (E + 3) / 4;

    cudaEventRecord(evFork, 0);
    cudaStreamWaitEvent(s2, evFork, 0);

    // --- branch B (s2): CSR build ---
    k_zero   <<<(N + 255) / 256, 256, 0, s2>>>(N);
    k_hist   <<<(e4 + 255) / 256, 256, 0, s2>>>(dst, E);
    k_scanA  <<<nb, SCAN_B, 0, s2>>>(N);
    k_scanC  <<<nb, SCAN_B, 0, s2>>>(N, E);
    k_scatter<<<(e4 + 255) / 256, 256, 0, s2>>>(src, dst, E);
    cudaEventRecord(evJoin, s2);

    // --- branch A (default stream): tensor-core projection ---
    k_wt      <<<64, 256>>>(Wfc);
    k_gemm_mma<<<(N + BM - 1) / BM, 256, SMEM_GEMM>>>(h, N);

    cudaStreamWaitEvent(0, evJoin, 0);
    k_agg<<<(N + 7) / 8, 256>>>(h, snorm, out, N);
}